// round 14
// baseline (speedup 1.0000x reference)
#include <cuda_runtime.h>
#include <math.h>

#define NB 512
#define ND 512
#define EPSF 1e-6f
#define HEPS (0.5f*1e-6f)

typedef unsigned long long u64t;

// ---------------- f32x2 packed helpers (sm_100a) ----------------
__device__ __forceinline__ u64t pk2(float lo, float hi){ u64t r; asm("mov.b64 %0, {%1,%2};" : "=l"(r) : "f"(lo), "f"(hi)); return r; }
__device__ __forceinline__ void upk2(u64t v, float&lo, float&hi){ asm("mov.b64 {%0,%1}, %2;" : "=f"(lo), "=f"(hi) : "l"(v)); }
__device__ __forceinline__ u64t fma2_(u64t a,u64t b,u64t c){ u64t d; asm("fma.rn.f32x2 %0,%1,%2,%3;" : "=l"(d) : "l"(a),"l"(b),"l"(c)); return d; }
__device__ __forceinline__ u64t mul2_(u64t a,u64t b){ u64t d; asm("mul.rn.f32x2 %0,%1,%2;" : "=l"(d) : "l"(a),"l"(b)); return d; }
__device__ __forceinline__ u64t add2_(u64t a,u64t b){ u64t d; asm("add.rn.f32x2 %0,%1,%2;" : "=l"(d) : "l"(a),"l"(b)); return d; }
__device__ __forceinline__ float rcpa(float x){ float r; asm("rcp.approx.f32 %0, %1;" : "=f"(r) : "f"(x)); return r; }
__device__ __forceinline__ float lg2a(float x){ float r; asm("lg2.approx.f32 %0, %1;" : "=f"(r) : "f"(x)); return r; }

// ---------------- scratch ----------------
__device__ float g_n1[NB * ND];    // normalized mu1, [i][d]
__device__ float g_h1[NB * ND];    // 0.5*sigma1 + HEPS, [i][d]
__device__ float g_n2t[NB * ND];   // NEGATED normalized mu2, TRANSPOSED [d][j]
__device__ float g_h2t[NB * ND];   // 0.5*sigma2 + HEPS, TRANSPOSED [d][j]
__device__ float g_ld1[NB], g_ld2[NB];
__device__ float g_ms1[NB], g_ms2[NB];
__device__ float g_inv2[NB];
// per-block partials: [chunk 0..15][row-or-col 0..511]
__device__ float g_rm[16 * NB], g_rs[16 * NB], g_dmin[16 * NB];
__device__ float g_cm[16 * NB], g_cs[16 * NB];
__device__ float g_dd[NB], g_diagl[NB];
__device__ float g_part6[16][6];
__device__ int   g_fc;

// ---------------- reduction helpers ----------------
__device__ __forceinline__ float wsum(float v) {
#pragma unroll
    for (int o = 16; o; o >>= 1) v += __shfl_down_sync(0xffffffffu, v, o);
    return v;
}

// ---------------- kernel 1: per-row reductions (both sides fused) ----------------
// 512 blocks, one per row pair index r; batched logs (2 values -> 1 lg2 per side).
__global__ void prep_kernel(const float* __restrict__ mu1, const float* __restrict__ s1,
                            const float* __restrict__ mu2, const float* __restrict__ s2)
{
    __shared__ float sh[6][8];
    __shared__ float s_i1, s_i2;
    const int r = blockIdx.x;
    const int t = threadIdx.x;
    if (r == 0 && t == 0) g_fc = 0;    // reset last-block counter each launch

    const int c0 = r * ND + t, c1 = c0 + 256;
    const float m1a = mu1[c0], m1b = mu1[c1];
    const float s1a = s1[c0],  s1b = s1[c1];
    const float m2a = mu2[c0], m2b = mu2[c1];
    const float s2a = s2[c0],  s2b = s2[c1];

    float v[6];
    v[0] = m1a * m1a + m1b * m1b;                       // ssq1
    v[1] = lg2a((s1a + EPSF) * (s1b + EPSF));           // log-det1 (base-2, batched)
    v[2] = s1a + s1b;                                   // mean-sigma1
    v[3] = m2a * m2a + m2b * m2b;                       // ssq2
    v[4] = lg2a((s2a + EPSF) * (s2b + EPSF));           // log-det2
    v[5] = s2a + s2b;                                   // mean-sigma2

    const int lane = t & 31, w = t >> 5;
#pragma unroll
    for (int k = 0; k < 6; k++) {
        const float rr = wsum(v[k]);
        if (!lane) sh[k][w] = rr;
    }
    __syncthreads();
    if (t == 0) {
        float s[6];
#pragma unroll
        for (int k = 0; k < 6; k++) {
            float a = 0.f;
            for (int q = 0; q < 8; q++) a += sh[k][q];
            s[k] = a;
        }
        const float i1 = 1.0f / fmaxf(sqrtf(s[0]), 1e-12f);
        const float i2 = 1.0f / fmaxf(sqrtf(s[3]), 1e-12f);
        s_i1 = i1; s_i2 = -i2;
        g_ld1[r] = s[1] * (float)M_LN2;
        g_ld2[r] = s[4] * (float)M_LN2;
        g_ms1[r] = s[2] * (1.0f / ND);
        g_ms2[r] = s[5] * (1.0f / ND);
        g_inv2[r] = -i2;
    }
    __syncthreads();
    const float i1 = s_i1;
    g_n1[c0] = m1a * i1;          g_n1[c1] = m1b * i1;
    g_h1[c0] = fmaf(0.5f, s1a, HEPS);  g_h1[c1] = fmaf(0.5f, s1b, HEPS);
}

// ---------------- kernel 2: transpose + scale side-2 arrays ----------------
__global__ void tscale_kernel(const float* __restrict__ mu2, const float* __restrict__ s2)
{
    __shared__ float tn[32][33], th[32][33];
    const int bx = blockIdx.x * 32;   // d origin
    const int by = blockIdx.y * 32;   // j origin
    const int tx = threadIdx.x, ty = threadIdx.y;   // 32 x 8
#pragma unroll
    for (int k = 0; k < 4; k++) {
        const int j = by + ty + k * 8;
        const float iv = g_inv2[j];
        tn[ty + k * 8][tx] = mu2[j * ND + bx + tx] * iv;
        th[ty + k * 8][tx] = fmaf(0.5f, s2[j * ND + bx + tx], HEPS);
    }
    __syncthreads();
#pragma unroll
    for (int k = 0; k < 4; k++) {
        const int d = bx + ty + k * 8;
        g_n2t[d * NB + by + tx] = tn[tx][ty + k * 8];
        g_h2t[d * NB + by + tx] = th[tx][ty + k * 8];
    }
}

// ---------------- kernel 3: Bhattacharyya O(B^2 D) pass + fused partials ----------------
// 32x32 tile, 256 threads = 2 anti-phase groups of 128 (warps 0-3 / 4-7) splitting D.
#define SN1(gg,i,d) pool[(gg)*2304 + (i)*36 + (d)]
#define SS1(gg,i,d) pool[(gg)*2304 + 1152 + (i)*36 + (d)]
#define SN2(gg,d,j) pool[4608 + (gg)*2048 + (d)*32 + (j)]
#define SS2(gg,d,j) pool[4608 + (gg)*2048 + 1024 + (d)*32 + (j)]

__global__ void __launch_bounds__(256, 2) bd_kernel(const float* __restrict__ lsp)
{
    __shared__ __align__(16) float pool[8704];

    const int bi = blockIdx.y * 32, bj = blockIdx.x * 32;
    const int tid = threadIdx.x;
    const int g  = tid >> 7;          // group (warps 0-3 vs 4-7)
    const int t  = tid & 127;
    const int tx = t & 15, ty = t >> 4;
    const int i0 = 4 * ty, j0 = 2 * tx;

    u64t t1a[4], d2a[4], lda[4];
#pragma unroll
    for (int x = 0; x < 4; x++) { t1a[x] = 0ull; d2a[x] = 0ull; lda[x] = 0ull; }

    for (int c = 0; c < 8; c++) {
        const int dc = g * 32 + c * 64;
        // loader: 2 x float4 per array per thread (32 rows x 8 segs)
#pragma unroll
        for (int k = 0; k < 2; k++) {
            const int s = t + k * 128;
            const int r = s >> 3, c4 = (s & 7) * 4;
            *(float4*)&SN1(g, r, c4) = *(const float4*)&g_n1[(bi + r) * ND + dc + c4];
            *(float4*)&SS1(g, r, c4) = *(const float4*)&g_h1[(bi + r) * ND + dc + c4];
            *(float4*)&SN2(g, r, c4) = *(const float4*)&g_n2t[(dc + r) * NB + bj + c4];
            *(float4*)&SS2(g, r, c4) = *(const float4*)&g_h2t[(dc + r) * NB + bj + c4];
        }
        asm volatile("bar.sync %0, 128;" :: "r"(g + 1) : "memory");

#pragma unroll 2
        for (int dg = 0; dg < 32; dg += 4) {
            u64t bn[4], bq[4];
#pragma unroll
            for (int dd = 0; dd < 4; dd++) {
                bn[dd] = *(const u64t*)&SN2(g, dg + dd, j0);
                bq[dd] = *(const u64t*)&SS2(g, dg + dd, j0);
            }
#pragma unroll
            for (int x = 0; x < 4; x++) {
                const float4 av = *(const float4*)&SN1(g, i0 + x, dg);
                const float4 pv = *(const float4*)&SS1(g, i0 + x, dg);
                const u64t s0  = add2_(pk2(pv.x, pv.x), bq[0]);
                const u64t s1_ = add2_(pk2(pv.y, pv.y), bq[1]);
                const u64t s2_ = add2_(pk2(pv.z, pv.z), bq[2]);
                const u64t s3_ = add2_(pk2(pv.w, pv.w), bq[3]);
                const u64t df0 = add2_(pk2(av.x, av.x), bn[0]);   // a - b (b negated)
                const u64t df1 = add2_(pk2(av.y, av.y), bn[1]);
                const u64t df2 = add2_(pk2(av.z, av.z), bn[2]);
                const u64t df3 = add2_(pk2(av.w, av.w), bn[3]);
                const u64t sq0 = mul2_(df0, df0);
                const u64t sq1 = mul2_(df1, df1);
                const u64t sq2 = mul2_(df2, df2);
                const u64t sq3 = mul2_(df3, df3);
                d2a[x] = add2_(d2a[x], add2_(add2_(sq0, sq1), add2_(sq2, sq3)));
                // numerator-pair Montgomery: sum sq_d/s_d = N/P, one rcp per 4 d's
                const u64t p01 = mul2_(s0, s1_);
                const u64t p23 = mul2_(s2_, s3_);
                const u64t P   = mul2_(p01, p23);
                float Pl, Ph; upk2(P, Pl, Ph);
                lda[x] = add2_(lda[x], pk2(lg2a(Pl), lg2a(Ph)));
                const u64t rP  = pk2(rcpa(Pl), rcpa(Ph));
                u64t N01 = mul2_(sq0, s1_); N01 = fma2_(sq1, s0,  N01);
                u64t N23 = mul2_(sq2, s3_); N23 = fma2_(sq3, s2_, N23);
                u64t N   = mul2_(N01, p23); N   = fma2_(N23, p01, N);
                t1a[x] = fma2_(N, rP, t1a[x]);
            }
        }
        asm volatile("bar.sync %0, 128;" :: "r"(g + 1) : "memory");
    }

    // ---- combine group partials ----
    __syncthreads();
    u64t (*comb)[12] = (u64t (*)[12])&pool[0];
    if (g == 1) {
#pragma unroll
        for (int x = 0; x < 4; x++) {
            comb[t][3 * x]     = t1a[x];
            comb[t][3 * x + 1] = d2a[x];
            comb[t][3 * x + 2] = lda[x];
        }
    }
    __syncthreads();
    if (g == 1) return;

    // ---- group 0: epilogue (logits + fused row/col partials) ----
#pragma unroll
    for (int x = 0; x < 4; x++) {
        t1a[x] = add2_(t1a[x], comb[t][3 * x]);
        d2a[x] = add2_(d2a[x], comb[t][3 * x + 1]);
        lda[x] = add2_(lda[x], comb[t][3 * x + 2]);
    }
    const float scale = lsp[0];
    const int j = bj + j0;
    const float ld2A = g_ld2[j], ld2B = g_ld2[j + 1];
    float lv[4][2], dv[4][2];
#pragma unroll
    for (int x = 0; x < 4; x++) {
        const int i = bi + i0 + x;
        const float ld1v = g_ld1[i];
        float tA, tB, dA, dB, lA, lB;
        upk2(t1a[x], tA, tB);
        upk2(d2a[x], dA, dB);
        upk2(lda[x], lA, lB);
        const float t2A = lA * (float)M_LN2 - 0.5f * (ld1v + ld2A);
        const float t2B = lB * (float)M_LN2 - 0.5f * (ld1v + ld2B);
        const float bdA = fmaf(0.125f, tA, 0.5f * t2A);
        const float bdB = fmaf(0.125f, tB, 0.5f * t2B);
        lv[x][0] = scale * __expf(-bdA * (1.0f / ND));
        lv[x][1] = scale * __expf(-bdB * (1.0f / ND));
        dv[x][0] = dA;
        dv[x][1] = dB;
    }

    // row partials: reduce over the 16 tx lanes (half-warp xor shuffles)
    const int bjG = blockIdx.x, biG = blockIdx.y;
#pragma unroll
    for (int x = 0; x < 4; x++) {
        const int i = bi + i0 + x;
        float rm = fmaxf(lv[x][0], lv[x][1]);
#pragma unroll
        for (int off = 8; off; off >>= 1) rm = fmaxf(rm, __shfl_xor_sync(0xffffffffu, rm, off));
        float rs = __expf(lv[x][0] - rm) + __expf(lv[x][1] - rm);
#pragma unroll
        for (int off = 8; off; off >>= 1) rs += __shfl_xor_sync(0xffffffffu, rs, off);
        float mA = (j == i)     ? 1e30f : dv[x][0];
        float mB = (j + 1 == i) ? 1e30f : dv[x][1];
        float dm = fminf(mA, mB);
#pragma unroll
        for (int off = 8; off; off >>= 1) dm = fminf(dm, __shfl_xor_sync(0xffffffffu, dm, off));
        if (tx == 0) {
            g_rm[bjG * NB + i]   = rm;
            g_rs[bjG * NB + i]   = rs;
            g_dmin[bjG * NB + i] = dm;
        }
        if (j == i)     { g_dd[i] = dv[x][0]; g_diagl[i] = lv[x][0]; }
        if (j + 1 == i) { g_dd[i] = dv[x][1]; g_diagl[i] = lv[x][1]; }
    }

    // col partials: per-thread over 4 i's, merge ty-pair via xor-16, then 4 warps via smem
    float* scm = &pool[4608];          // [4][32]
    float* scs = &pool[4608 + 128];
    const int w = t >> 5;
#pragma unroll
    for (int jj = 0; jj < 2; jj++) {
        float cm = fmaxf(fmaxf(lv[0][jj], lv[1][jj]), fmaxf(lv[2][jj], lv[3][jj]));
        float cs = __expf(lv[0][jj] - cm) + __expf(lv[1][jj] - cm)
                 + __expf(lv[2][jj] - cm) + __expf(lv[3][jj] - cm);
        const float om = __shfl_xor_sync(0xffffffffu, cm, 16);
        const float os = __shfl_xor_sync(0xffffffffu, cs, 16);
        const float nm = fmaxf(cm, om);
        cs = cs * __expf(cm - nm) + os * __expf(om - nm);
        cm = nm;
        if ((t & 31) < 16) { scm[w * 32 + j0 + jj] = cm; scs[w * 32 + j0 + jj] = cs; }
    }
    asm volatile("bar.sync 1, 128;" ::: "memory");
    if (t < 32) {
        float m = scm[t], s = scs[t];
#pragma unroll
        for (int k = 1; k < 4; k++) {
            const float om = scm[k * 32 + t], os = scs[k * 32 + t];
            const float nm = fmaxf(m, om);
            s = s * __expf(m - nm) + os * __expf(om - nm);
            m = nm;
        }
        g_cm[biG * NB + bj + t] = m;
        g_cs[biG * NB + bj + t] = s;
    }
}

// ---------------- kernel 4: partial-combine + last-block final (16 blocks x 128 thr) ----------------
__global__ void final_kernel(float* __restrict__ out)
{
    __shared__ float fsh[6][4];
    __shared__ int s_last;
    const int b = blockIdx.x;
    const int tt = threadIdx.x;
    const int idx = b * 128 + tt;     // 0..2047
    const int r = idx >> 2, sub = idx & 3;
    const int k0 = sub * 4;

    float m = -1e30f, s = 0.f, mc = -1e30f, sc = 0.f, dmin = 1e30f;
#pragma unroll
    for (int k = k0; k < k0 + 4; k++) {
        const float rm = g_rm[k * NB + r];
        const float nm = fmaxf(m, rm);
        s = s * __expf(m - nm) + g_rs[k * NB + r] * __expf(rm - nm);
        m = nm;
        const float cm = g_cm[k * NB + r];
        const float nc = fmaxf(mc, cm);
        sc = sc * __expf(mc - nc) + g_cs[k * NB + r] * __expf(cm - nc);
        mc = nc;
        dmin = fminf(dmin, g_dmin[k * NB + r]);
    }
#pragma unroll
    for (int off = 1; off <= 2; off <<= 1) {
        const float om = __shfl_xor_sync(0xffffffffu, m, off);
        const float os = __shfl_xor_sync(0xffffffffu, s, off);
        const float nm = fmaxf(m, om);
        s = s * __expf(m - nm) + os * __expf(om - nm);
        m = nm;
        const float oc  = __shfl_xor_sync(0xffffffffu, mc, off);
        const float osc = __shfl_xor_sync(0xffffffffu, sc, off);
        const float nc = fmaxf(mc, oc);
        sc = sc * __expf(mc - nc) + osc * __expf(oc - nc);
        mc = nc;
        dmin = fminf(dmin, __shfl_xor_sync(0xffffffffu, dmin, off));
    }

    // per-row 6-vector on sub==0 lanes; zero elsewhere, then block-reduce
    float v[6] = {0.f, 0.f, 0.f, 0.f, 0.f, 0.f};
    if (sub == 0) {
        const float lse_row = m + __logf(s);
        const float lse_col = mc + __logf(sc);
        const float u = __expf(-__expf(dmin - g_dd[r]));   // exp(-diag_sim2/negmax)
        const float diag = g_diagl[r];
        const float as = 0.5f * (g_ms1[r] + g_ms2[r]);
        v[0] = lse_row - diag;
        v[1] = lse_col - diag;
        v[2] = u;
        v[3] = u * u;
        v[4] = as * as;
        v[5] = u * as;
    }
    const int lane = tt & 31, w = tt >> 5;
#pragma unroll
    for (int k = 0; k < 6; k++) {
        const float rr = wsum(v[k]);
        if (!lane) fsh[k][w] = rr;
    }
    __syncthreads();
    if (tt < 6) g_part6[b][tt] = fsh[tt][0] + fsh[tt][1] + fsh[tt][2] + fsh[tt][3];

    // last block combines the 16 deterministic partials
    __threadfence();
    __syncthreads();
    if (tt == 0) s_last = (atomicAdd(&g_fc, 1) == 15);
    __syncthreads();
    if (!s_last) return;
    __threadfence();

    if (tt == 0) {
        float sm[6] = {0.f, 0.f, 0.f, 0.f, 0.f, 0.f};
        for (int q = 0; q < 16; q++)
#pragma unroll
            for (int k = 0; k < 6; k++) sm[k] += g_part6[q][k];
        const float loss_pro = 0.5f * ((sm[0] + sm[1]) * (1.0f / NB));
        const float cosv = sm[5] / (fmaxf(sqrtf(sm[3]), 1e-12f) * fmaxf(sqrtf(sm[4]), 1e-12f));
        out[0] = loss_pro;
        out[1] = 2.4f * (1.0f - cosv);
        out[2] = 0.5f * (sm[2] * (1.0f / NB));
    }
}

// ---------------- launch ----------------
extern "C" void kernel_launch(void* const* d_in, const int* in_sizes, int n_in,
                              void* d_out, int out_size)
{
    const float* mu1 = (const float*)d_in[0];
    const float* s1  = (const float*)d_in[1];
    const float* mu2 = (const float*)d_in[2];
    const float* s2  = (const float*)d_in[3];
    const float* ls  = (const float*)d_in[4];
    float* out = (float*)d_out;

    prep_kernel<<<NB, 256>>>(mu1, s1, mu2, s2);
    tscale_kernel<<<dim3(16, 16), dim3(32, 8)>>>(mu2, s2);
    bd_kernel<<<dim3(16, 16), 256>>>(ls);
    final_kernel<<<16, 128>>>(out);
}

// round 15
// speedup vs baseline: 1.0614x; 1.0614x over previous
#include <cuda_runtime.h>
#include <math.h>

#define NB 512
#define ND 512
#define EPSF 1e-6f
#define HEPS (0.5f*1e-6f)

typedef unsigned long long u64t;

// ---------------- f32x2 packed helpers (sm_100a) ----------------
__device__ __forceinline__ u64t pk2(float lo, float hi){ u64t r; asm("mov.b64 %0, {%1,%2};" : "=l"(r) : "f"(lo), "f"(hi)); return r; }
__device__ __forceinline__ void upk2(u64t v, float&lo, float&hi){ asm("mov.b64 {%0,%1}, %2;" : "=f"(lo), "=f"(hi) : "l"(v)); }
__device__ __forceinline__ u64t fma2_(u64t a,u64t b,u64t c){ u64t d; asm("fma.rn.f32x2 %0,%1,%2,%3;" : "=l"(d) : "l"(a),"l"(b),"l"(c)); return d; }
__device__ __forceinline__ u64t mul2_(u64t a,u64t b){ u64t d; asm("mul.rn.f32x2 %0,%1,%2;" : "=l"(d) : "l"(a),"l"(b)); return d; }
__device__ __forceinline__ u64t add2_(u64t a,u64t b){ u64t d; asm("add.rn.f32x2 %0,%1,%2;" : "=l"(d) : "l"(a),"l"(b)); return d; }
__device__ __forceinline__ float rcpa(float x){ float r; asm("rcp.approx.f32 %0, %1;" : "=f"(r) : "f"(x)); return r; }
__device__ __forceinline__ float lg2a(float x){ float r; asm("lg2.approx.f32 %0, %1;" : "=f"(r) : "f"(x)); return r; }

// ---------------- scratch ----------------
__device__ float g_n1[NB * ND];    // normalized mu1, [i][d]
__device__ float g_h1[NB * ND];    // 0.5*sigma1 + HEPS, [i][d]
__device__ float g_n2t[NB * ND];   // NEGATED normalized mu2, TRANSPOSED [d][j]
__device__ float g_h2t[NB * ND];   // 0.5*sigma2 + HEPS, TRANSPOSED [d][j]
__device__ float g_ld1[NB], g_ld2[NB];
__device__ float g_ms1[NB], g_ms2[NB];
__device__ float g_inv2[NB];
// accumulated softmax sums (fixed shift = scale) + row-min of d^2
__device__ float g_rs[NB], g_cs[NB];
__device__ int   g_dmin[NB];
__device__ float g_dd[NB], g_diagl[NB];

// ---------------- reduction helpers ----------------
__device__ __forceinline__ float wsum(float v) {
#pragma unroll
    for (int o = 16; o; o >>= 1) v += __shfl_down_sync(0xffffffffu, v, o);
    return v;
}

// ---------------- kernel 1: per-row reductions + side-1 arrays + accumulator reset ----------------
__global__ void prep_kernel(const float* __restrict__ mu1, const float* __restrict__ s1,
                            const float* __restrict__ mu2, const float* __restrict__ s2)
{
    __shared__ float sh[3][8];
    __shared__ float s_inv;
    const int row = blockIdx.x;
    const bool first = row < NB;
    const int r = first ? row : row - NB;
    const float* mu = (first ? mu1 : mu2) + r * ND;
    const float* sg = (first ? s1 : s2) + r * ND;
    const int t = threadIdx.x;

    if (first && t == 0) {               // reset accumulators for this row each launch
        g_rs[r] = 0.0f;
        g_cs[r] = 0.0f;
        g_dmin[r] = 0x7f800000;          // +inf bits
    }

    float ssq = 0.f, lsum = 0.f, msum = 0.f;
    for (int c = t; c < ND; c += 256) {
        float x = mu[c];
        ssq += x * x;
        float sv = sg[c];
        lsum += __logf(sv + EPSF);
        msum += sv;
        if (first) g_h1[r * ND + c] = fmaf(0.5f, sv, HEPS);
    }
    ssq = wsum(ssq); lsum = wsum(lsum); msum = wsum(msum);
    const int lane = t & 31, w = t >> 5;
    if (!lane) { sh[0][w] = ssq; sh[1][w] = lsum; sh[2][w] = msum; }
    __syncthreads();
    if (t == 0) {
        float a = 0.f, b = 0.f, c2 = 0.f;
        for (int k = 0; k < 8; k++) { a += sh[0][k]; b += sh[1][k]; c2 += sh[2][k]; }
        float inv = 1.0f / fmaxf(sqrtf(a), 1e-12f);
        s_inv = inv;
        (first ? g_ld1 : g_ld2)[r] = b;
        (first ? g_ms1 : g_ms2)[r] = c2 * (1.0f / ND);
        if (!first) g_inv2[r] = -inv;
    }
    __syncthreads();
    if (first) {
        const float inv = s_inv;
        for (int c = t; c < ND; c += 256) g_n1[r * ND + c] = mu[c] * inv;
    }
}

// ---------------- kernel 2: transpose + scale side-2 arrays ----------------
__global__ void tscale_kernel(const float* __restrict__ mu2, const float* __restrict__ s2)
{
    __shared__ float tn[32][33], th[32][33];
    const int bx = blockIdx.x * 32;   // d origin
    const int by = blockIdx.y * 32;   // j origin
    const int tx = threadIdx.x, ty = threadIdx.y;   // 32 x 8
#pragma unroll
    for (int k = 0; k < 4; k++) {
        const int j = by + ty + k * 8;
        const float iv = g_inv2[j];
        tn[ty + k * 8][tx] = mu2[j * ND + bx + tx] * iv;
        th[ty + k * 8][tx] = fmaf(0.5f, s2[j * ND + bx + tx], HEPS);
    }
    __syncthreads();
#pragma unroll
    for (int k = 0; k < 4; k++) {
        const int d = bx + ty + k * 8;
        g_n2t[d * NB + by + tx] = tn[tx][ty + k * 8];
        g_h2t[d * NB + by + tx] = th[tx][ty + k * 8];
    }
}

// ---------------- kernel 3: Bhattacharyya O(B^2 D) pass + direct atomic accumulation ----------------
// 32x32 tile, 256 threads = 2 anti-phase groups of 128 (warps 0-3 / 4-7) splitting D.
#define SN1(gg,i,d) pool[(gg)*2304 + (i)*36 + (d)]
#define SS1(gg,i,d) pool[(gg)*2304 + 1152 + (i)*36 + (d)]
#define SN2(gg,d,j) pool[4608 + (gg)*2048 + (d)*32 + (j)]
#define SS2(gg,d,j) pool[4608 + (gg)*2048 + 1024 + (d)*32 + (j)]

__global__ void __launch_bounds__(256, 2) bd_kernel(const float* __restrict__ lsp)
{
    __shared__ __align__(16) float pool[8704];

    const int bi = blockIdx.y * 32, bj = blockIdx.x * 32;
    const int tid = threadIdx.x;
    const int g  = tid >> 7;          // group (warps 0-3 vs 4-7)
    const int t  = tid & 127;
    const int tx = t & 15, ty = t >> 4;
    const int i0 = 4 * ty, j0 = 2 * tx;

    u64t t1a[4], d2a[4], lda[4];
#pragma unroll
    for (int x = 0; x < 4; x++) { t1a[x] = 0ull; d2a[x] = 0ull; lda[x] = 0ull; }

    for (int c = 0; c < 8; c++) {
        const int dc = g * 32 + c * 64;
        // loader: 2 x float4 per array per thread (32 rows x 8 segs)
#pragma unroll
        for (int k = 0; k < 2; k++) {
            const int s = t + k * 128;
            const int r = s >> 3, c4 = (s & 7) * 4;
            *(float4*)&SN1(g, r, c4) = *(const float4*)&g_n1[(bi + r) * ND + dc + c4];
            *(float4*)&SS1(g, r, c4) = *(const float4*)&g_h1[(bi + r) * ND + dc + c4];
            *(float4*)&SN2(g, r, c4) = *(const float4*)&g_n2t[(dc + r) * NB + bj + c4];
            *(float4*)&SS2(g, r, c4) = *(const float4*)&g_h2t[(dc + r) * NB + bj + c4];
        }
        asm volatile("bar.sync %0, 128;" :: "r"(g + 1) : "memory");

#pragma unroll 2
        for (int dg = 0; dg < 32; dg += 4) {
            u64t bn[4], bq[4];
#pragma unroll
            for (int dd = 0; dd < 4; dd++) {
                bn[dd] = *(const u64t*)&SN2(g, dg + dd, j0);
                bq[dd] = *(const u64t*)&SS2(g, dg + dd, j0);
            }
#pragma unroll
            for (int x = 0; x < 4; x++) {
                const float4 av = *(const float4*)&SN1(g, i0 + x, dg);
                const float4 pv = *(const float4*)&SS1(g, i0 + x, dg);
                const u64t s0  = add2_(pk2(pv.x, pv.x), bq[0]);
                const u64t s1_ = add2_(pk2(pv.y, pv.y), bq[1]);
                const u64t s2_ = add2_(pk2(pv.z, pv.z), bq[2]);
                const u64t s3_ = add2_(pk2(pv.w, pv.w), bq[3]);
                const u64t df0 = add2_(pk2(av.x, av.x), bn[0]);   // a - b (b negated)
                const u64t df1 = add2_(pk2(av.y, av.y), bn[1]);
                const u64t df2 = add2_(pk2(av.z, av.z), bn[2]);
                const u64t df3 = add2_(pk2(av.w, av.w), bn[3]);
                const u64t sq0 = mul2_(df0, df0);
                const u64t sq1 = mul2_(df1, df1);
                const u64t sq2 = mul2_(df2, df2);
                const u64t sq3 = mul2_(df3, df3);
                d2a[x] = add2_(d2a[x], add2_(add2_(sq0, sq1), add2_(sq2, sq3)));
                // numerator-pair Montgomery: sum sq_d/s_d = N/P, one rcp per 4 d's
                const u64t p01 = mul2_(s0, s1_);
                const u64t p23 = mul2_(s2_, s3_);
                const u64t P   = mul2_(p01, p23);
                float Pl, Ph; upk2(P, Pl, Ph);
                lda[x] = add2_(lda[x], pk2(lg2a(Pl), lg2a(Ph)));
                const u64t rP  = pk2(rcpa(Pl), rcpa(Ph));
                u64t N01 = mul2_(sq0, s1_); N01 = fma2_(sq1, s0,  N01);
                u64t N23 = mul2_(sq2, s3_); N23 = fma2_(sq3, s2_, N23);
                u64t N   = mul2_(N01, p23); N   = fma2_(N23, p01, N);
                t1a[x] = fma2_(N, rP, t1a[x]);
            }
        }
        asm volatile("bar.sync %0, 128;" :: "r"(g + 1) : "memory");
    }

    // ---- combine group partials ----
    __syncthreads();
    u64t (*comb)[12] = (u64t (*)[12])&pool[0];
    if (g == 1) {
#pragma unroll
        for (int x = 0; x < 4; x++) {
            comb[t][3 * x]     = t1a[x];
            comb[t][3 * x + 1] = d2a[x];
            comb[t][3 * x + 2] = lda[x];
        }
    }
    __syncthreads();
    if (g == 1) return;

    // ---- group 0: epilogue with fixed-shift (M = scale) softmax sums ----
#pragma unroll
    for (int x = 0; x < 4; x++) {
        t1a[x] = add2_(t1a[x], comb[t][3 * x]);
        d2a[x] = add2_(d2a[x], comb[t][3 * x + 1]);
        lda[x] = add2_(lda[x], comb[t][3 * x + 2]);
    }
    const float scale = lsp[0];
    const int j = bj + j0;
    const float ld2A = g_ld2[j], ld2B = g_ld2[j + 1];
    float ev[4][2], dv[4][2];   // ev = exp(l - scale)
#pragma unroll
    for (int x = 0; x < 4; x++) {
        const int i = bi + i0 + x;
        const float ld1v = g_ld1[i];
        float tA, tB, dA, dB, lA, lB;
        upk2(t1a[x], tA, tB);
        upk2(d2a[x], dA, dB);
        upk2(lda[x], lA, lB);
        const float t2A = lA * (float)M_LN2 - 0.5f * (ld1v + ld2A);
        const float t2B = lB * (float)M_LN2 - 0.5f * (ld1v + ld2B);
        const float bdA = fmaf(0.125f, tA, 0.5f * t2A);
        const float bdB = fmaf(0.125f, tB, 0.5f * t2B);
        const float lvA = scale * __expf(-bdA * (1.0f / ND));   // logit
        const float lvB = scale * __expf(-bdB * (1.0f / ND));
        ev[x][0] = __expf(lvA - scale);
        ev[x][1] = __expf(lvB - scale);
        dv[x][0] = dA;
        dv[x][1] = dB;
        if (j == i)     { g_dd[i] = dA; g_diagl[i] = lvA; }
        if (j + 1 == i) { g_dd[i] = dB; g_diagl[i] = lvB; }
    }

    // row sums + row d2-min: reduce over the 16 tx lanes
#pragma unroll
    for (int x = 0; x < 4; x++) {
        const int i = bi + i0 + x;
        float rs = ev[x][0] + ev[x][1];
#pragma unroll
        for (int off = 8; off; off >>= 1) rs += __shfl_xor_sync(0xffffffffu, rs, off);
        float mA = (j == i)     ? 1e30f : dv[x][0];
        float mB = (j + 1 == i) ? 1e30f : dv[x][1];
        float dm = fminf(mA, mB);
#pragma unroll
        for (int off = 8; off; off >>= 1) dm = fminf(dm, __shfl_xor_sync(0xffffffffu, dm, off));
        if (tx == 0) {
            atomicAdd(&g_rs[i], rs);
            atomicMin(&g_dmin[i], __float_as_int(dm));   // valid: dm > 0
        }
    }

    // col sums: per-thread over 4 i's, merge ty-pair via xor-16, atomicAdd per half-warp
#pragma unroll
    for (int jj = 0; jj < 2; jj++) {
        float cs = ev[0][jj] + ev[1][jj] + ev[2][jj] + ev[3][jj];
        cs += __shfl_xor_sync(0xffffffffu, cs, 16);
        if ((t & 31) < 16) atomicAdd(&g_cs[j + jj], cs);
    }
}

// ---------------- kernel 4: final — 1 block, fixed-shift LSEs + losses ----------------
__global__ void final_kernel(const float* __restrict__ lsp, float* __restrict__ out)
{
    __shared__ float fsh[6][16];
    const int t = threadIdx.x;   // 512 threads
    const float scale = lsp[0];

    const float lse_row = scale + __logf(g_rs[t]);
    const float lse_col = scale + __logf(g_cs[t]);
    const float dmin = __int_as_float(g_dmin[t]);
    const float u = __expf(-__expf(dmin - g_dd[t]));   // exp(-diag_sim2/negmax)

    const float diag = g_diagl[t];
    const float as = 0.5f * (g_ms1[t] + g_ms2[t]);
    float v[6] = { lse_row - diag, lse_col - diag, u, u * u, as * as, u * as };
    const int lane = t & 31, w = t >> 5;
#pragma unroll
    for (int k = 0; k < 6; k++) {
        const float r = wsum(v[k]);
        if (!lane) fsh[k][w] = r;
    }
    __syncthreads();
    if (t == 0) {
        float s[6];
        for (int k = 0; k < 6; k++) {
            float a = 0.f;
            for (int q = 0; q < 16; q++) a += fsh[k][q];
            s[k] = a;
        }
        const float loss_pro = 0.5f * ((s[0] + s[1]) * (1.0f / NB));
        const float cosv = s[5] / (fmaxf(sqrtf(s[3]), 1e-12f) * fmaxf(sqrtf(s[4]), 1e-12f));
        out[0] = loss_pro;
        out[1] = 2.4f * (1.0f - cosv);
        out[2] = 0.5f * (s[2] * (1.0f / NB));
    }
}

// ---------------- launch ----------------
extern "C" void kernel_launch(void* const* d_in, const int* in_sizes, int n_in,
                              void* d_out, int out_size)
{
    const float* mu1 = (const float*)d_in[0];
    const float* s1  = (const float*)d_in[1];
    const float* mu2 = (const float*)d_in[2];
    const float* s2  = (const float*)d_in[3];
    const float* ls  = (const float*)d_in[4];
    float* out = (float*)d_out;

    prep_kernel<<<2 * NB, 256>>>(mu1, s1, mu2, s2);
    tscale_kernel<<<dim3(16, 16), dim3(32, 8)>>>(mu2, s2);
    bd_kernel<<<dim3(16, 16), 256>>>(ls);
    final_kernel<<<1, NB>>>(ls, out);
}

// round 16
// speedup vs baseline: 1.1704x; 1.1027x over previous
#include <cuda_runtime.h>
#include <math.h>

#define NB 512
#define ND 512
#define EPSF 1e-6f
#define HEPS (0.5f*1e-6f)

typedef unsigned long long u64t;

// ---------------- f32x2 packed helpers (sm_100a) ----------------
__device__ __forceinline__ u64t pk2(float lo, float hi){ u64t r; asm("mov.b64 %0, {%1,%2};" : "=l"(r) : "f"(lo), "f"(hi)); return r; }
__device__ __forceinline__ void upk2(u64t v, float&lo, float&hi){ asm("mov.b64 {%0,%1}, %2;" : "=f"(lo), "=f"(hi) : "l"(v)); }
__device__ __forceinline__ u64t fma2_(u64t a,u64t b,u64t c){ u64t d; asm("fma.rn.f32x2 %0,%1,%2,%3;" : "=l"(d) : "l"(a),"l"(b),"l"(c)); return d; }
__device__ __forceinline__ u64t mul2_(u64t a,u64t b){ u64t d; asm("mul.rn.f32x2 %0,%1,%2;" : "=l"(d) : "l"(a),"l"(b)); return d; }
__device__ __forceinline__ u64t add2_(u64t a,u64t b){ u64t d; asm("add.rn.f32x2 %0,%1,%2;" : "=l"(d) : "l"(a),"l"(b)); return d; }
__device__ __forceinline__ float rcpa(float x){ float r; asm("rcp.approx.f32 %0, %1;" : "=f"(r) : "f"(x)); return r; }
__device__ __forceinline__ float lg2a(float x){ float r; asm("lg2.approx.f32 %0, %1;" : "=f"(r) : "f"(x)); return r; }

// ---------------- scratch ----------------
__device__ float g_n1[NB * ND];    // normalized mu1, [i][d]
__device__ float g_h1[NB * ND];    // 0.5*sigma1 + HEPS, [i][d]
__device__ float g_n2t[NB * ND];   // NEGATED normalized mu2, TRANSPOSED [d][j]
__device__ float g_h2t[NB * ND];   // 0.5*sigma2 + HEPS, TRANSPOSED [d][j]
__device__ float g_ld1[NB], g_ld2[NB];
__device__ float g_ms1[NB], g_ms2[NB];
__device__ float g_inv2[NB];
// accumulated softmax sums (fixed shift = scale) + row-min of d^2
__device__ float g_rs[NB], g_cs[NB];
__device__ int   g_dmin[NB];
__device__ float g_dd[NB], g_diagl[NB];

// ---------------- reduction helpers ----------------
__device__ __forceinline__ float wsum(float v) {
#pragma unroll
    for (int o = 16; o; o >>= 1) v += __shfl_down_sync(0xffffffffu, v, o);
    return v;
}

// ---------------- kernel 1: per-row reductions, both sides fused (512 blocks) ----------------
__global__ void prep_kernel(const float* __restrict__ mu1, const float* __restrict__ s1,
                            const float* __restrict__ mu2, const float* __restrict__ s2)
{
    __shared__ float sh[6][8];
    __shared__ float s_i1;
    const int r = blockIdx.x;
    const int t = threadIdx.x;

    if (t == 0) {                    // reset accumulators for this row each launch
        g_rs[r] = 0.0f;
        g_cs[r] = 0.0f;
        g_dmin[r] = 0x7f800000;      // +inf bits
    }

    const int c0 = r * ND + t, c1 = c0 + 256;
    const float m1a = mu1[c0], m1b = mu1[c1];
    const float s1a = s1[c0],  s1b = s1[c1];
    const float m2a = mu2[c0], m2b = mu2[c1];
    const float s2a = s2[c0],  s2b = s2[c1];

    float v[6];
    v[0] = m1a * m1a + m1b * m1b;                       // ssq1
    v[1] = lg2a((s1a + EPSF) * (s1b + EPSF));           // log-det1 (base-2, batched)
    v[2] = s1a + s1b;                                   // sum-sigma1
    v[3] = m2a * m2a + m2b * m2b;                       // ssq2
    v[4] = lg2a((s2a + EPSF) * (s2b + EPSF));           // log-det2
    v[5] = s2a + s2b;                                   // sum-sigma2

    const int lane = t & 31, w = t >> 5;
#pragma unroll
    for (int k = 0; k < 6; k++) {
        const float rr = wsum(v[k]);
        if (!lane) sh[k][w] = rr;
    }
    __syncthreads();
    if (t == 0) {
        float s[6];
#pragma unroll
        for (int k = 0; k < 6; k++) {
            float a = 0.f;
            for (int q = 0; q < 8; q++) a += sh[k][q];
            s[k] = a;
        }
        const float i1 = 1.0f / fmaxf(sqrtf(s[0]), 1e-12f);
        const float i2 = 1.0f / fmaxf(sqrtf(s[3]), 1e-12f);
        s_i1 = i1;
        g_ld1[r] = s[1] * (float)M_LN2;
        g_ld2[r] = s[4] * (float)M_LN2;
        g_ms1[r] = s[2] * (1.0f / ND);
        g_ms2[r] = s[5] * (1.0f / ND);
        g_inv2[r] = -i2;
    }
    __syncthreads();
    const float i1 = s_i1;
    g_n1[c0] = m1a * i1;               g_n1[c1] = m1b * i1;
    g_h1[c0] = fmaf(0.5f, s1a, HEPS);  g_h1[c1] = fmaf(0.5f, s1b, HEPS);
}

// ---------------- kernel 2: transpose + scale side-2 arrays ----------------
__global__ void tscale_kernel(const float* __restrict__ mu2, const float* __restrict__ s2)
{
    __shared__ float tn[32][33], th[32][33];
    const int bx = blockIdx.x * 32;   // d origin
    const int by = blockIdx.y * 32;   // j origin
    const int tx = threadIdx.x, ty = threadIdx.y;   // 32 x 8
#pragma unroll
    for (int k = 0; k < 4; k++) {
        const int j = by + ty + k * 8;
        const float iv = g_inv2[j];
        tn[ty + k * 8][tx] = mu2[j * ND + bx + tx] * iv;
        th[ty + k * 8][tx] = fmaf(0.5f, s2[j * ND + bx + tx], HEPS);
    }
    __syncthreads();
#pragma unroll
    for (int k = 0; k < 4; k++) {
        const int d = bx + ty + k * 8;
        g_n2t[d * NB + by + tx] = tn[tx][ty + k * 8];
        g_h2t[d * NB + by + tx] = th[tx][ty + k * 8];
    }
}

// ---------------- kernel 3: Bhattacharyya O(B^2 D) pass, 8-wide Montgomery batch ----------------
// 32x32 tile, 256 threads = 2 anti-phase groups of 128 (warps 0-3 / 4-7) splitting D.
#define SN1(gg,i,d) pool[(gg)*2304 + (i)*36 + (d)]
#define SS1(gg,i,d) pool[(gg)*2304 + 1152 + (i)*36 + (d)]
#define SN2(gg,d,j) pool[4608 + (gg)*2048 + (d)*32 + (j)]
#define SS2(gg,d,j) pool[4608 + (gg)*2048 + 1024 + (d)*32 + (j)]

// one 4-d sub-block: returns P (product of 4 s) and N (numerator) ; updates d2a
__device__ __forceinline__ void bd_sub4(const float4 av, const float4 pv,
                                        const u64t* bn, const u64t* bq,
                                        u64t& d2a, u64t& P, u64t& N)
{
    const u64t s0  = add2_(pk2(pv.x, pv.x), bq[0]);
    const u64t s1_ = add2_(pk2(pv.y, pv.y), bq[1]);
    const u64t s2_ = add2_(pk2(pv.z, pv.z), bq[2]);
    const u64t s3_ = add2_(pk2(pv.w, pv.w), bq[3]);
    const u64t df0 = add2_(pk2(av.x, av.x), bn[0]);   // a - b (b stored negated)
    const u64t df1 = add2_(pk2(av.y, av.y), bn[1]);
    const u64t df2 = add2_(pk2(av.z, av.z), bn[2]);
    const u64t df3 = add2_(pk2(av.w, av.w), bn[3]);
    const u64t sq0 = mul2_(df0, df0);
    const u64t sq1 = mul2_(df1, df1);
    const u64t sq2 = mul2_(df2, df2);
    const u64t sq3 = mul2_(df3, df3);
    d2a = add2_(d2a, add2_(add2_(sq0, sq1), add2_(sq2, sq3)));
    const u64t p01 = mul2_(s0, s1_);
    const u64t p23 = mul2_(s2_, s3_);
    P = mul2_(p01, p23);
    u64t N01 = mul2_(sq0, s1_); N01 = fma2_(sq1, s0,  N01);
    u64t N23 = mul2_(sq2, s3_); N23 = fma2_(sq3, s2_, N23);
    N = mul2_(N01, p23); N = fma2_(N23, p01, N);
}

__global__ void __launch_bounds__(256, 2) bd_kernel(const float* __restrict__ lsp)
{
    __shared__ __align__(16) float pool[8704];

    const int bi = blockIdx.y * 32, bj = blockIdx.x * 32;
    const int tid = threadIdx.x;
    const int g  = tid >> 7;          // group (warps 0-3 vs 4-7)
    const int t  = tid & 127;
    const int tx = t & 15, ty = t >> 4;
    const int i0 = 4 * ty, j0 = 2 * tx;

    u64t t1a[4], d2a[4], lda[4];
#pragma unroll
    for (int x = 0; x < 4; x++) { t1a[x] = 0ull; d2a[x] = 0ull; lda[x] = 0ull; }

    for (int c = 0; c < 8; c++) {
        const int dc = g * 32 + c * 64;
        // loader: 2 x float4 per array per thread (32 rows x 8 segs)
#pragma unroll
        for (int k = 0; k < 2; k++) {
            const int s = t + k * 128;
            const int r = s >> 3, c4 = (s & 7) * 4;
            *(float4*)&SN1(g, r, c4) = *(const float4*)&g_n1[(bi + r) * ND + dc + c4];
            *(float4*)&SS1(g, r, c4) = *(const float4*)&g_h1[(bi + r) * ND + dc + c4];
            *(float4*)&SN2(g, r, c4) = *(const float4*)&g_n2t[(dc + r) * NB + bj + c4];
            *(float4*)&SS2(g, r, c4) = *(const float4*)&g_h2t[(dc + r) * NB + bj + c4];
        }
        asm volatile("bar.sync %0, 128;" :: "r"(g + 1) : "memory");

#pragma unroll
        for (int dg = 0; dg < 32; dg += 8) {
            u64t bn[8], bq[8];
#pragma unroll
            for (int dd = 0; dd < 8; dd++) {
                bn[dd] = *(const u64t*)&SN2(g, dg + dd, j0);
                bq[dd] = *(const u64t*)&SS2(g, dg + dd, j0);
            }
#pragma unroll
            for (int x = 0; x < 4; x++) {
                u64t Pa, Na, Pb, Nb;
                {
                    const float4 av = *(const float4*)&SN1(g, i0 + x, dg);
                    const float4 pv = *(const float4*)&SS1(g, i0 + x, dg);
                    bd_sub4(av, pv, bn, bq, d2a[x], Pa, Na);
                }
                {
                    const float4 av = *(const float4*)&SN1(g, i0 + x, dg + 4);
                    const float4 pv = *(const float4*)&SS1(g, i0 + x, dg + 4);
                    bd_sub4(av, pv, bn + 4, bq + 4, d2a[x], Pb, Nb);
                }
                // 8-wide batch: one rcp + one lg2 per 8 d's (per packed half)
                const u64t P8 = mul2_(Pa, Pb);
                float Pl, Ph; upk2(P8, Pl, Ph);
                lda[x] = add2_(lda[x], pk2(lg2a(Pl), lg2a(Ph)));
                const u64t rP = pk2(rcpa(Pl), rcpa(Ph));
                u64t N8 = mul2_(Na, Pb); N8 = fma2_(Nb, Pa, N8);
                t1a[x] = fma2_(N8, rP, t1a[x]);
            }
        }
        asm volatile("bar.sync %0, 128;" :: "r"(g + 1) : "memory");
    }

    // ---- combine group partials ----
    __syncthreads();
    u64t (*comb)[12] = (u64t (*)[12])&pool[0];
    if (g == 1) {
#pragma unroll
        for (int x = 0; x < 4; x++) {
            comb[t][3 * x]     = t1a[x];
            comb[t][3 * x + 1] = d2a[x];
            comb[t][3 * x + 2] = lda[x];
        }
    }
    __syncthreads();
    if (g == 1) return;

    // ---- group 0: epilogue with fixed-shift (M = scale) softmax sums ----
#pragma unroll
    for (int x = 0; x < 4; x++) {
        t1a[x] = add2_(t1a[x], comb[t][3 * x]);
        d2a[x] = add2_(d2a[x], comb[t][3 * x + 1]);
        lda[x] = add2_(lda[x], comb[t][3 * x + 2]);
    }
    const float scale = lsp[0];
    const int j = bj + j0;
    const float ld2A = g_ld2[j], ld2B = g_ld2[j + 1];
    float ev[4][2], dv[4][2];   // ev = exp(l - scale)
#pragma unroll
    for (int x = 0; x < 4; x++) {
        const int i = bi + i0 + x;
        const float ld1v = g_ld1[i];
        float tA, tB, dA, dB, lA, lB;
        upk2(t1a[x], tA, tB);
        upk2(d2a[x], dA, dB);
        upk2(lda[x], lA, lB);
        const float t2A = lA * (float)M_LN2 - 0.5f * (ld1v + ld2A);
        const float t2B = lB * (float)M_LN2 - 0.5f * (ld1v + ld2B);
        const float bdA = fmaf(0.125f, tA, 0.5f * t2A);
        const float bdB = fmaf(0.125f, tB, 0.5f * t2B);
        const float lvA = scale * __expf(-bdA * (1.0f / ND));   // logit
        const float lvB = scale * __expf(-bdB * (1.0f / ND));
        ev[x][0] = __expf(lvA - scale);
        ev[x][1] = __expf(lvB - scale);
        dv[x][0] = dA;
        dv[x][1] = dB;
        if (j == i)     { g_dd[i] = dA; g_diagl[i] = lvA; }
        if (j + 1 == i) { g_dd[i] = dB; g_diagl[i] = lvB; }
    }

    // row sums + row d2-min: reduce over the 16 tx lanes
#pragma unroll
    for (int x = 0; x < 4; x++) {
        const int i = bi + i0 + x;
        float rs = ev[x][0] + ev[x][1];
#pragma unroll
        for (int off = 8; off; off >>= 1) rs += __shfl_xor_sync(0xffffffffu, rs, off);
        float mA = (j == i)     ? 1e30f : dv[x][0];
        float mB = (j + 1 == i) ? 1e30f : dv[x][1];
        float dm = fminf(mA, mB);
#pragma unroll
        for (int off = 8; off; off >>= 1) dm = fminf(dm, __shfl_xor_sync(0xffffffffu, dm, off));
        if (tx == 0) {
            atomicAdd(&g_rs[i], rs);
            atomicMin(&g_dmin[i], __float_as_int(dm));   // valid: dm > 0
        }
    }

    // col sums: per-thread over 4 i's, merge ty-pair via xor-16, atomicAdd per half-warp
#pragma unroll
    for (int jj = 0; jj < 2; jj++) {
        float cs = ev[0][jj] + ev[1][jj] + ev[2][jj] + ev[3][jj];
        cs += __shfl_xor_sync(0xffffffffu, cs, 16);
        if ((t & 31) < 16) atomicAdd(&g_cs[j + jj], cs);
    }
}

// ---------------- kernel 4: final — 1 block, fixed-shift LSEs + losses ----------------
__global__ void final_kernel(const float* __restrict__ lsp, float* __restrict__ out)
{
    __shared__ float fsh[6][16];
    const int t = threadIdx.x;   // 512 threads
    const float scale = lsp[0];

    const float lse_row = scale + __logf(g_rs[t]);
    const float lse_col = scale + __logf(g_cs[t]);
    const float dmin = __int_as_float(g_dmin[t]);
    const float u = __expf(-__expf(dmin - g_dd[t]));   // exp(-diag_sim2/negmax)

    const float diag = g_diagl[t];
    const float as = 0.5f * (g_ms1[t] + g_ms2[t]);
    float v[6] = { lse_row - diag, lse_col - diag, u, u * u, as * as, u * as };
    const int lane = t & 31, w = t >> 5;
#pragma unroll
    for (int k = 0; k < 6; k++) {
        const float r = wsum(v[k]);
        if (!lane) fsh[k][w] = r;
    }
    __syncthreads();
    if (t == 0) {
        float s[6];
        for (int k = 0; k < 6; k++) {
            float a = 0.f;
            for (int q = 0; q < 16; q++) a += fsh[k][q];
            s[k] = a;
        }
        const float loss_pro = 0.5f * ((s[0] + s[1]) * (1.0f / NB));
        const float cosv = s[5] / (fmaxf(sqrtf(s[3]), 1e-12f) * fmaxf(sqrtf(s[4]), 1e-12f));
        out[0] = loss_pro;
        out[1] = 2.4f * (1.0f - cosv);
        out[2] = 0.5f * (s[2] * (1.0f / NB));
    }
}

// ---------------- launch ----------------
extern "C" void kernel_launch(void* const* d_in, const int* in_sizes, int n_in,
                              void* d_out, int out_size)
{
    const float* mu1 = (const float*)d_in[0];
    const float* s1  = (const float*)d_in[1];
    const float* mu2 = (const float*)d_in[2];
    const float* s2  = (const float*)d_in[3];
    const float* ls  = (const float*)d_in[4];
    float* out = (float*)d_out;

    prep_kernel<<<NB, 256>>>(mu1, s1, mu2, s2);
    tscale_kernel<<<dim3(16, 16), dim3(32, 8)>>>(mu2, s2);
    bd_kernel<<<dim3(16, 16), 256>>>(ls);
    final_kernel<<<1, NB>>>(ls, out);
}

// round 17
// speedup vs baseline: 1.2276x; 1.0489x over previous
#include <cuda_runtime.h>
#include <math.h>

#define NB 512
#define ND 512
#define EPSF 1e-6f
#define HEPS (0.5f*1e-6f)

typedef unsigned long long u64t;

// ---------------- f32x2 packed helpers (sm_100a) ----------------
__device__ __forceinline__ u64t pk2(float lo, float hi){ u64t r; asm("mov.b64 %0, {%1,%2};" : "=l"(r) : "f"(lo), "f"(hi)); return r; }
__device__ __forceinline__ void upk2(u64t v, float&lo, float&hi){ asm("mov.b64 {%0,%1}, %2;" : "=f"(lo), "=f"(hi) : "l"(v)); }
__device__ __forceinline__ u64t fma2_(u64t a,u64t b,u64t c){ u64t d; asm("fma.rn.f32x2 %0,%1,%2,%3;" : "=l"(d) : "l"(a),"l"(b),"l"(c)); return d; }
__device__ __forceinline__ u64t mul2_(u64t a,u64t b){ u64t d; asm("mul.rn.f32x2 %0,%1,%2;" : "=l"(d) : "l"(a),"l"(b)); return d; }
__device__ __forceinline__ u64t add2_(u64t a,u64t b){ u64t d; asm("add.rn.f32x2 %0,%1,%2;" : "=l"(d) : "l"(a),"l"(b)); return d; }
__device__ __forceinline__ float rcpa(float x){ float r; asm("rcp.approx.f32 %0, %1;" : "=f"(r) : "f"(x)); return r; }
__device__ __forceinline__ float lg2a(float x){ float r; asm("lg2.approx.f32 %0, %1;" : "=f"(r) : "f"(x)); return r; }

// ---------------- scratch ----------------
__device__ float g_n1[NB * ND];    // normalized mu1, [i][d]
__device__ float g_h1[NB * ND];    // 0.5*sigma1 + HEPS, [i][d]
__device__ float g_n2t[NB * ND];   // NEGATED normalized mu2, TRANSPOSED [d][j]
__device__ float g_h2t[NB * ND];   // 0.5*sigma2 + HEPS, TRANSPOSED [d][j]
__device__ float g_ld1[NB], g_ld2[NB];
__device__ float g_ms1[NB], g_ms2[NB];
__device__ float g_inv2[NB];
// accumulated softmax sums (fixed shift = scale) + row-min of d^2
__device__ float g_rs[NB], g_cs[NB];
__device__ int   g_dmin[NB];
__device__ float g_dd[NB], g_diagl[NB];

// ---------------- reduction helpers ----------------
__device__ __forceinline__ float wsum(float v) {
#pragma unroll
    for (int o = 16; o; o >>= 1) v += __shfl_down_sync(0xffffffffu, v, o);
    return v;
}

// ---------------- kernel 1: per-row reductions, both sides fused (512 blocks) ----------------
__global__ void prep_kernel(const float* __restrict__ mu1, const float* __restrict__ s1,
                            const float* __restrict__ mu2, const float* __restrict__ s2)
{
    __shared__ float sh[6][8];
    __shared__ float s_i1;
    const int r = blockIdx.x;
    const int t = threadIdx.x;

    if (t == 0) {                    // reset accumulators for this row each launch
        g_rs[r] = 0.0f;
        g_cs[r] = 0.0f;
        g_dmin[r] = 0x7f800000;      // +inf bits
    }

    const int c0 = r * ND + t, c1 = c0 + 256;
    const float m1a = mu1[c0], m1b = mu1[c1];
    const float s1a = s1[c0],  s1b = s1[c1];
    const float m2a = mu2[c0], m2b = mu2[c1];
    const float s2a = s2[c0],  s2b = s2[c1];

    float v[6];
    v[0] = m1a * m1a + m1b * m1b;                       // ssq1
    v[1] = lg2a((s1a + EPSF) * (s1b + EPSF));           // log-det1 (base-2, batched)
    v[2] = s1a + s1b;                                   // sum-sigma1
    v[3] = m2a * m2a + m2b * m2b;                       // ssq2
    v[4] = lg2a((s2a + EPSF) * (s2b + EPSF));           // log-det2
    v[5] = s2a + s2b;                                   // sum-sigma2

    const int lane = t & 31, w = t >> 5;
#pragma unroll
    for (int k = 0; k < 6; k++) {
        const float rr = wsum(v[k]);
        if (!lane) sh[k][w] = rr;
    }
    __syncthreads();
    if (t == 0) {
        float s[6];
#pragma unroll
        for (int k = 0; k < 6; k++) {
            float a = 0.f;
            for (int q = 0; q < 8; q++) a += sh[k][q];
            s[k] = a;
        }
        const float i1 = 1.0f / fmaxf(sqrtf(s[0]), 1e-12f);
        const float i2 = 1.0f / fmaxf(sqrtf(s[3]), 1e-12f);
        s_i1 = i1;
        g_ld1[r] = s[1] * (float)M_LN2;
        g_ld2[r] = s[4] * (float)M_LN2;
        g_ms1[r] = s[2] * (1.0f / ND);
        g_ms2[r] = s[5] * (1.0f / ND);
        g_inv2[r] = -i2;
    }
    __syncthreads();
    const float i1 = s_i1;
    g_n1[c0] = m1a * i1;               g_n1[c1] = m1b * i1;
    g_h1[c0] = fmaf(0.5f, s1a, HEPS);  g_h1[c1] = fmaf(0.5f, s1b, HEPS);
}

// ---------------- kernel 2: transpose + scale side-2 arrays ----------------
__global__ void tscale_kernel(const float* __restrict__ mu2, const float* __restrict__ s2)
{
    __shared__ float tn[32][33], th[32][33];
    const int bx = blockIdx.x * 32;   // d origin
    const int by = blockIdx.y * 32;   // j origin
    const int tx = threadIdx.x, ty = threadIdx.y;   // 32 x 8
#pragma unroll
    for (int k = 0; k < 4; k++) {
        const int j = by + ty + k * 8;
        const float iv = g_inv2[j];
        tn[ty + k * 8][tx] = mu2[j * ND + bx + tx] * iv;
        th[ty + k * 8][tx] = fmaf(0.5f, s2[j * ND + bx + tx], HEPS);
    }
    __syncthreads();
#pragma unroll
    for (int k = 0; k < 4; k++) {
        const int d = bx + ty + k * 8;
        g_n2t[d * NB + by + tx] = tn[tx][ty + k * 8];
        g_h2t[d * NB + by + tx] = th[tx][ty + k * 8];
    }
}

// ---------------- kernel 3: Bhattacharyya O(B^2 D) pass, 16-wide Montgomery chain ----------------
// 32x32 tile, 256 threads = 2 anti-phase groups of 128 (warps 0-3 / 4-7) splitting D.
#define SN1(gg,i,d) pool[(gg)*2304 + (i)*36 + (d)]
#define SS1(gg,i,d) pool[(gg)*2304 + 1152 + (i)*36 + (d)]
#define SN2(gg,d,j) pool[4608 + (gg)*2048 + (d)*32 + (j)]
#define SS2(gg,d,j) pool[4608 + (gg)*2048 + 1024 + (d)*32 + (j)]

// one 4-d sub-block: returns P (product of 4 s) and N (numerator) ; updates d2a
__device__ __forceinline__ void bd_sub4(const float4 av, const float4 pv,
                                        const u64t* bn, const u64t* bq,
                                        u64t& d2a, u64t& P, u64t& N)
{
    const u64t s0  = add2_(pk2(pv.x, pv.x), bq[0]);
    const u64t s1_ = add2_(pk2(pv.y, pv.y), bq[1]);
    const u64t s2_ = add2_(pk2(pv.z, pv.z), bq[2]);
    const u64t s3_ = add2_(pk2(pv.w, pv.w), bq[3]);
    const u64t df0 = add2_(pk2(av.x, av.x), bn[0]);   // a - b (b stored negated)
    const u64t df1 = add2_(pk2(av.y, av.y), bn[1]);
    const u64t df2 = add2_(pk2(av.z, av.z), bn[2]);
    const u64t df3 = add2_(pk2(av.w, av.w), bn[3]);
    const u64t sq0 = mul2_(df0, df0);
    const u64t sq1 = mul2_(df1, df1);
    const u64t sq2 = mul2_(df2, df2);
    const u64t sq3 = mul2_(df3, df3);
    d2a = add2_(d2a, add2_(add2_(sq0, sq1), add2_(sq2, sq3)));
    const u64t p01 = mul2_(s0, s1_);
    const u64t p23 = mul2_(s2_, s3_);
    P = mul2_(p01, p23);
    u64t N01 = mul2_(sq0, s1_); N01 = fma2_(sq1, s0,  N01);
    u64t N23 = mul2_(sq2, s3_); N23 = fma2_(sq3, s2_, N23);
    N = mul2_(N01, p23); N = fma2_(N23, p01, N);
}

__global__ void __launch_bounds__(256, 2) bd_kernel(const float* __restrict__ lsp)
{
    __shared__ __align__(16) float pool[8704];

    const int bi = blockIdx.y * 32, bj = blockIdx.x * 32;
    const int tid = threadIdx.x;
    const int g  = tid >> 7;          // group (warps 0-3 vs 4-7)
    const int t  = tid & 127;
    const int tx = t & 15, ty = t >> 4;
    const int i0 = 4 * ty, j0 = 2 * tx;

    u64t t1a[4], d2a[4], lda[4];
#pragma unroll
    for (int x = 0; x < 4; x++) { t1a[x] = 0ull; d2a[x] = 0ull; lda[x] = 0ull; }

    for (int c = 0; c < 8; c++) {
        const int dc = g * 32 + c * 64;
        // loader: 2 x float4 per array per thread (32 rows x 8 segs)
#pragma unroll
        for (int k = 0; k < 2; k++) {
            const int s = t + k * 128;
            const int r = s >> 3, c4 = (s & 7) * 4;
            *(float4*)&SN1(g, r, c4) = *(const float4*)&g_n1[(bi + r) * ND + dc + c4];
            *(float4*)&SS1(g, r, c4) = *(const float4*)&g_h1[(bi + r) * ND + dc + c4];
            *(float4*)&SN2(g, r, c4) = *(const float4*)&g_n2t[(dc + r) * NB + bj + c4];
            *(float4*)&SS2(g, r, c4) = *(const float4*)&g_h2t[(dc + r) * NB + bj + c4];
        }
        asm volatile("bar.sync %0, 128;" :: "r"(g + 1) : "memory");

        // two 16-d halves; one rcp + one lg2 per 16 d's (per packed half)
#pragma unroll
        for (int half = 0; half < 2; half++) {
            const int dgb = half * 16;
            u64t Pr[4], Nr[4];
#pragma unroll
            for (int q = 0; q < 4; q++) {
                const int dg = dgb + q * 4;
                u64t bn[4], bq[4];
#pragma unroll
                for (int dd = 0; dd < 4; dd++) {
                    bn[dd] = *(const u64t*)&SN2(g, dg + dd, j0);
                    bq[dd] = *(const u64t*)&SS2(g, dg + dd, j0);
                }
#pragma unroll
                for (int x = 0; x < 4; x++) {
                    const float4 av = *(const float4*)&SN1(g, i0 + x, dg);
                    const float4 pv = *(const float4*)&SS1(g, i0 + x, dg);
                    u64t P4, N4;
                    bd_sub4(av, pv, bn, bq, d2a[x], P4, N4);
                    if (q == 0) {
                        Pr[x] = P4; Nr[x] = N4;
                    } else {
                        Nr[x] = fma2_(N4, Pr[x], mul2_(Nr[x], P4));
                        Pr[x] = mul2_(Pr[x], P4);
                    }
                }
            }
#pragma unroll
            for (int x = 0; x < 4; x++) {
                float Pl, Ph; upk2(Pr[x], Pl, Ph);
                lda[x] = add2_(lda[x], pk2(lg2a(Pl), lg2a(Ph)));
                const u64t rP = pk2(rcpa(Pl), rcpa(Ph));
                t1a[x] = fma2_(Nr[x], rP, t1a[x]);
            }
        }
        asm volatile("bar.sync %0, 128;" :: "r"(g + 1) : "memory");
    }

    // ---- combine group partials ----
    __syncthreads();
    u64t (*comb)[12] = (u64t (*)[12])&pool[0];
    if (g == 1) {
#pragma unroll
        for (int x = 0; x < 4; x++) {
            comb[t][3 * x]     = t1a[x];
            comb[t][3 * x + 1] = d2a[x];
            comb[t][3 * x + 2] = lda[x];
        }
    }
    __syncthreads();
    if (g == 1) return;

    // ---- group 0: epilogue with fixed-shift (M = scale) softmax sums ----
#pragma unroll
    for (int x = 0; x < 4; x++) {
        t1a[x] = add2_(t1a[x], comb[t][3 * x]);
        d2a[x] = add2_(d2a[x], comb[t][3 * x + 1]);
        lda[x] = add2_(lda[x], comb[t][3 * x + 2]);
    }
    const float scale = lsp[0];
    const int j = bj + j0;
    const float ld2A = g_ld2[j], ld2B = g_ld2[j + 1];
    float ev[4][2], dv[4][2];   // ev = exp(l - scale)
#pragma unroll
    for (int x = 0; x < 4; x++) {
        const int i = bi + i0 + x;
        const float ld1v = g_ld1[i];
        float tA, tB, dA, dB, lA, lB;
        upk2(t1a[x], tA, tB);
        upk2(d2a[x], dA, dB);
        upk2(lda[x], lA, lB);
        const float t2A = lA * (float)M_LN2 - 0.5f * (ld1v + ld2A);
        const float t2B = lB * (float)M_LN2 - 0.5f * (ld1v + ld2B);
        const float bdA = fmaf(0.125f, tA, 0.5f * t2A);
        const float bdB = fmaf(0.125f, tB, 0.5f * t2B);
        const float lvA = scale * __expf(-bdA * (1.0f / ND));   // logit
        const float lvB = scale * __expf(-bdB * (1.0f / ND));
        ev[x][0] = __expf(lvA - scale);
        ev[x][1] = __expf(lvB - scale);
        dv[x][0] = dA;
        dv[x][1] = dB;
        if (j == i)     { g_dd[i] = dA; g_diagl[i] = lvA; }
        if (j + 1 == i) { g_dd[i] = dB; g_diagl[i] = lvB; }
    }

    // row sums + row d2-min: reduce over the 16 tx lanes
#pragma unroll
    for (int x = 0; x < 4; x++) {
        const int i = bi + i0 + x;
        float rs = ev[x][0] + ev[x][1];
#pragma unroll
        for (int off = 8; off; off >>= 1) rs += __shfl_xor_sync(0xffffffffu, rs, off);
        float mA = (j == i)     ? 1e30f : dv[x][0];
        float mB = (j + 1 == i) ? 1e30f : dv[x][1];
        float dm = fminf(mA, mB);
#pragma unroll
        for (int off = 8; off; off >>= 1) dm = fminf(dm, __shfl_xor_sync(0xffffffffu, dm, off));
        if (tx == 0) {
            atomicAdd(&g_rs[i], rs);
            atomicMin(&g_dmin[i], __float_as_int(dm));   // valid: dm > 0
        }
    }

    // col sums: per-thread over 4 i's, merge ty-pair via xor-16, atomicAdd per half-warp
#pragma unroll
    for (int jj = 0; jj < 2; jj++) {
        float cs = ev[0][jj] + ev[1][jj] + ev[2][jj] + ev[3][jj];
        cs += __shfl_xor_sync(0xffffffffu, cs, 16);
        if ((t & 31) < 16) atomicAdd(&g_cs[j + jj], cs);
    }
}

// ---------------- kernel 4: final — 1 block, fixed-shift LSEs + losses ----------------
__global__ void final_kernel(const float* __restrict__ lsp, float* __restrict__ out)
{
    __shared__ float fsh[6][16];
    const int t = threadIdx.x;   // 512 threads
    const float scale = lsp[0];

    const float lse_row = scale + __logf(g_rs[t]);
    const float lse_col = scale + __logf(g_cs[t]);
    const float dmin = __int_as_float(g_dmin[t]);
    const float u = __expf(-__expf(dmin - g_dd[t]));   // exp(-diag_sim2/negmax)

    const float diag = g_diagl[t];
    const float as = 0.5f * (g_ms1[t] + g_ms2[t]);
    float v[6] = { lse_row - diag, lse_col - diag, u, u * u, as * as, u * as };
    const int lane = t & 31, w = t >> 5;
#pragma unroll
    for (int k = 0; k < 6; k++) {
        const float r = wsum(v[k]);
        if (!lane) fsh[k][w] = r;
    }
    __syncthreads();
    if (t == 0) {
        float s[6];
        for (int k = 0; k < 6; k++) {
            float a = 0.f;
            for (int q = 0; q < 16; q++) a += fsh[k][q];
            s[k] = a;
        }
        const float loss_pro = 0.5f * ((s[0] + s[1]) * (1.0f / NB));
        const float cosv = s[5] / (fmaxf(sqrtf(s[3]), 1e-12f) * fmaxf(sqrtf(s[4]), 1e-12f));
        out[0] = loss_pro;
        out[1] = 2.4f * (1.0f - cosv);
        out[2] = 0.5f * (s[2] * (1.0f / NB));
    }
}

// ---------------- launch ----------------
extern "C" void kernel_launch(void* const* d_in, const int* in_sizes, int n_in,
                              void* d_out, int out_size)
{
    const float* mu1 = (const float*)d_in[0];
    const float* s1  = (const float*)d_in[1];
    const float* mu2 = (const float*)d_in[2];
    const float* s2  = (const float*)d_in[3];
    const float* ls  = (const float*)d_in[4];
    float* out = (float*)d_out;

    prep_kernel<<<NB, 256>>>(mu1, s1, mu2, s2);
    tscale_kernel<<<dim3(16, 16), dim3(32, 8)>>>(mu2, s2);
    bd_kernel<<<dim3(16, 16), 256>>>(ls);
    final_kernel<<<1, NB>>>(ls, out);
}